// round 17
// baseline (speedup 1.0000x reference)
#include <cuda_runtime.h>
#include <cuda_fp16.h>
#include <math.h>
#include <stdint.h>

#define Bb   2
#define Ss   2048
#define Dd   2048
#define NQh  16
#define NKVh 8
#define Hh   256
#define WIN  1024

// ---------------- scratch (static device arrays; no allocations) ----------------
__device__ float g_cs[Ss * 128];
__device__ float g_sn[Ss * 128];

__device__ __half g_xh [(size_t)4096 * 2048];
__device__ __half g_wqh[(size_t)4096 * 2048];   // Wq^T rope-permuted rows
__device__ __half g_wkh[(size_t)2048 * 2048];   // Wk^T rope-permuted rows
__device__ __half g_wvh[(size_t)2048 * 2048];
__device__ __half g_woh[(size_t)2048 * 4096];
__device__ __half g_qh [(size_t)4096 * 4096];   // roped+scaled q (interleaved dims)
__device__ __half g_kh [(size_t)4096 * 2048];   // roped k (interleaved dims)
__device__ __half g_vh [(size_t)4096 * 2048];
__device__ __half g_avh[(size_t)4096 * 4096];

// ======================= mma.sync helpers ========================================
__device__ __forceinline__ uint32_t smem_u32(const void* p) {
    return (uint32_t)__cvta_generic_to_shared(p);
}
__device__ __forceinline__ void mma_f16(float* c, const uint32_t* a, uint32_t b0, uint32_t b1) {
    asm volatile(
        "mma.sync.aligned.m16n8k16.row.col.f32.f16.f16.f32 "
        "{%0,%1,%2,%3}, {%4,%5,%6,%7}, {%8,%9}, {%0,%1,%2,%3};"
        : "+f"(c[0]), "+f"(c[1]), "+f"(c[2]), "+f"(c[3])
        : "r"(a[0]), "r"(a[1]), "r"(a[2]), "r"(a[3]), "r"(b0), "r"(b1));
}
__device__ __forceinline__ void ldsm_x4(uint32_t* r, uint32_t addr) {
    asm volatile("ldmatrix.sync.aligned.m8n8.x4.shared.b16 {%0,%1,%2,%3}, [%4];"
        : "=r"(r[0]), "=r"(r[1]), "=r"(r[2]), "=r"(r[3]) : "r"(addr));
}
__device__ __forceinline__ void ldsm_x4_t(uint32_t* r, uint32_t addr) {
    asm volatile("ldmatrix.sync.aligned.m8n8.x4.trans.shared.b16 {%0,%1,%2,%3}, [%4];"
        : "=r"(r[0]), "=r"(r[1]), "=r"(r[2]), "=r"(r[3]) : "r"(addr));
}
__device__ __forceinline__ void cp16(uint32_t dst, const void* src) {
    asm volatile("cp.async.cg.shared.global [%0], [%1], 16;" :: "r"(dst), "l"(src));
}
__device__ __forceinline__ void cp_commit() {
    asm volatile("cp.async.commit_group;" ::: "memory");
}
__device__ __forceinline__ void cp_wait0() {
    asm volatile("cp.async.wait_group 0;" ::: "memory");
}
__device__ __forceinline__ void cp_wait1() {
    asm volatile("cp.async.wait_group 1;" ::: "memory");
}
__device__ __forceinline__ uint32_t pack_h2(float f0, float f1) {
    __half h0 = __float2half_rn(f0);
    __half h1 = __float2half_rn(f1);
    return (uint32_t)__half_as_ushort(h0) | ((uint32_t)__half_as_ushort(h1) << 16);
}

// softcap+exp fused: exp(50*tanh(l/50)) = exp2(l*(C0 + C1 l^2 + C2 l^4 + C3 l^6))
__device__ __forceinline__ float softcap_exp(float l, bool ok) {
    const float C0 = 1.4426950408889634f;
    const float C1 = -1.9235933878519342e-4f;
    const float C2 = 3.0777494205630946e-8f;
    const float C3 = -4.9831443418516624e-12f;
    float s2 = l * l;
    float m = l * fmaf(s2, fmaf(s2, fmaf(s2, C3, C2), C1), C0);
    m = ok ? m : -1000.0f;
    float r;
    asm("ex2.approx.f32 %0, %1;" : "=f"(r) : "f"(m));
    return r;
}

// ======================= unified conversion kernel ===============================
__global__ void conv_all_kernel(const float4* __restrict__ x4,
                                const float* __restrict__ Wq,
                                const float* __restrict__ Wk,
                                const float* __restrict__ Wv,
                                const float* __restrict__ Wo,
                                __half* __restrict__ xh,
                                __half* __restrict__ wqh,
                                __half* __restrict__ wkh,
                                __half* __restrict__ wvh,
                                __half* __restrict__ woh)
{
    __shared__ float t[32][33];
    const int blk = blockIdx.x;

    if (blk >= 32768) {                       // ---- rope table (fp64) ----
        int idx = (blk - 32768) * 256 + threadIdx.x;
        int tt = idx >> 7;
        int ii = idx & 127;
        double inv = exp(-((double)(2 * ii) / 256.0) * log(10000.0));
        double phd = (double)tt * inv;
        g_cs[idx] = (float)cos(phd);
        g_sn[idx] = (float)sin(phd);
        return;
    }
    if (blk < 8192) {                         // ---- x: straight fp16 round ----
        int i = blk * 256 + threadIdx.x;
        float4 v = x4[i];
        uint2 vh;
        vh.x = pack_h2(v.x, v.y);
        vh.y = pack_h2(v.z, v.w);
        *(uint2*)(xh + (size_t)4 * i) = vh;
        return;
    }

    const float* in;
    __half* out;
    int K, Nh, z, kx, ny, perm;
    if (blk < 16384) {
        int rel = blk - 8192;  in = Wq; out = wqh; K = Dd; Nh = Hh; perm = 1;
        z = rel >> 9; int tile = rel & 511; kx = tile & 63; ny = tile >> 6;
    } else if (blk < 20480) {
        int rel = blk - 16384; in = Wk; out = wkh; K = Dd; Nh = Hh; perm = 1;
        z = rel >> 9; int tile = rel & 511; kx = tile & 63; ny = tile >> 6;
    } else if (blk < 24576) {
        int rel = blk - 20480; in = Wv; out = wvh; K = Dd; Nh = Hh; perm = 0;
        z = rel >> 9; int tile = rel & 511; kx = tile & 63; ny = tile >> 6;
    } else {
        int rel = blk - 24576; in = Wo; out = woh; K = 4096; Nh = Dd; perm = 0;
        z = 0; kx = rel & 127; ny = rel >> 7;
    }

    const int k0 = kx * 32;
    const int n0 = ny * 32;
    const int tx = threadIdx.x & 31;
    const int ty = threadIdx.x >> 5;
    const float* p = in + (size_t)z * K * Nh;
    #pragma unroll
    for (int i = 0; i < 4; ++i)
        t[ty + 8 * i][tx] = p[(size_t)(k0 + ty + 8 * i) * Nh + n0 + tx];
    __syncthreads();
    #pragma unroll
    for (int i = 0; i < 4; ++i) {
        float v = t[tx][ty + 8 * i];
        int n = n0 + ty + 8 * i;
        int pr = perm ? ((n < 128) ? 2 * n : 2 * (n - 128) + 1) : n;
        out[(size_t)(z * Nh + pr) * K + k0 + tx] = __float2half_rn(v);
    }
}

// ======================= mma.sync fp16 GEMM (3-stage pipeline) ===================
#define GT_TILE_B   16384
#define GT_BUF_B    (2 * GT_TILE_B)       // A + B per stage = 32 KB
#define GT_SMEM     (3 * GT_BUF_B)        // 96 KB, 3 stages

template <typename EPI>
__device__ __forceinline__
void gemm_core(const __half* __restrict__ Abase, const __half* __restrict__ Bbase,
               int K, EPI epi)
{
    extern __shared__ char sm[];
    const uint32_t sb  = smem_u32(sm);
    const int tid  = threadIdx.x;
    const int wid  = tid >> 5;
    const int lane = tid & 31;
    const int wm   = wid & 1;
    const int wn   = wid >> 1;

    const __half* srcs[2] = { Abase, Bbase };

    auto load_chunk = [&](int buf, int kt) {
        const uint32_t base = sb + buf * GT_BUF_B;
        #pragma unroll
        for (int i = 0; i < 8; ++i) {
            int u    = tid + i * 256;
            int tile = u >> 10;
            int row  = (u >> 3) & 127;
            int unit = u & 7;
            uint32_t dst = base + tile * GT_TILE_B + row * 128 + ((unit ^ (row & 7)) << 4);
            cp16(dst, srcs[tile] + (size_t)row * K + kt * 64 + unit * 8);
        }
        cp_commit();
    };

    float acc[4][4][4];
    #pragma unroll
    for (int mi = 0; mi < 4; ++mi)
        #pragma unroll
        for (int ni = 0; ni < 4; ++ni)
            #pragma unroll
            for (int e = 0; e < 4; ++e) acc[mi][ni][e] = 0.f;

    const int KT = K >> 6;
    load_chunk(0, 0);
    load_chunk(1, 1);

    const int lrow = lane & 15;
    const int lk   = lane >> 4;

    int buf = 0;
    for (int kt = 0; kt < KT; ++kt) {
        if (kt >= KT - 1) cp_wait0(); else cp_wait1();
        __syncthreads();                    // single barrier per chunk

        const uint32_t aBase = sb + buf * GT_BUF_B;
        const uint32_t bBase = aBase + GT_TILE_B;

        #pragma unroll
        for (int ks = 0; ks < 4; ++ks) {
            uint32_t ah[4][4], bh[2][4];
            #pragma unroll
            for (int mi = 0; mi < 4; ++mi) {
                int r = wm * 64 + mi * 16 + lrow;
                ldsm_x4(ah[mi], aBase + r * 128 + (((ks * 2 + lk) ^ (r & 7)) << 4));
            }
            #pragma unroll
            for (int nh = 0; nh < 2; ++nh) {
                int r = wn * 32 + nh * 16 + lrow;
                ldsm_x4(bh[nh], bBase + r * 128 + (((ks * 2 + lk) ^ (r & 7)) << 4));
            }
            #pragma unroll
            for (int mi = 0; mi < 4; ++mi)
                #pragma unroll
                for (int ni = 0; ni < 4; ++ni) {
                    const int s = ni & 1;
                    mma_f16(acc[mi][ni], ah[mi], bh[ni >> 1][s], bh[ni >> 1][s + 2]);
                }
        }

        if (kt + 2 < KT) {
            int nb = buf + 2; if (nb >= 3) nb -= 3;
            load_chunk(nb, kt + 2);
        }
        if (++buf == 3) buf = 0;
    }

    #pragma unroll
    for (int mi = 0; mi < 4; ++mi)
        #pragma unroll
        for (int ni = 0; ni < 4; ++ni) {
            int rl = wm * 64 + mi * 16 + (lane >> 2);
            int cl = wn * 32 + ni * 8 + (lane & 3) * 2;
            epi(rl, cl, acc[mi][ni]);
        }
}

__global__ __launch_bounds__(256, 2)
void gemm_tc(const __half* __restrict__ Ah, const __half* __restrict__ Bh,
             float* __restrict__ C, int K, int ldc)
{
    const int bm = blockIdx.x * 128, bn = blockIdx.y * 128;
    gemm_core(Ah + (size_t)bm * K, Bh + (size_t)bn * K, K,
        [&](int rl, int cl, const float* a) {
            int row = bm + rl, col = bn + cl;
            *(float2*)(C + (size_t)row * ldc + col)       = make_float2(a[0], a[1]);
            *(float2*)(C + (size_t)(row + 8) * ldc + col) = make_float2(a[2], a[3]);
        });
}

__global__ __launch_bounds__(256, 2)
void gemm_qkv(const __half* __restrict__ xh,
              const __half* __restrict__ wqh, const __half* __restrict__ wkh,
              const __half* __restrict__ wvh,
              __half* __restrict__ qh, __half* __restrict__ kh, __half* __restrict__ vh)
{
    const int K  = Dd;
    const int bm = blockIdx.x * 128;
    const int y  = blockIdx.y;
    const __half* B;
    __half* Cc;
    int bn, ldc, mode;
    float scale = 1.0f;
    if (y < 32)      { bn = y * 128;        B = wqh; Cc = qh; ldc = 4096; mode = 1; scale = 0.0625f; }
    else if (y < 48) { bn = (y - 32) * 128; B = wkh; Cc = kh; ldc = 2048; mode = 1; }
    else             { bn = (y - 48) * 128; B = wvh; Cc = vh; ldc = 2048; mode = 0; }

    gemm_core(xh + (size_t)bm * K, B + (size_t)bn * K, K,
        [&](int rl, int cl, const float* a) {
            int row = bm + rl, col = bn + cl;
            if (mode) {
                const int i = (col & (Hh - 1)) >> 1;
                const int t0r = row & (Ss - 1);
                const int t1r = (row + 8) & (Ss - 1);
                float cs0 = g_cs[t0r * 128 + i], sn0 = g_sn[t0r * 128 + i];
                float cs1 = g_cs[t1r * 128 + i], sn1 = g_sn[t1r * 128 + i];
                *(uint32_t*)(Cc + (size_t)row * ldc + col) =
                    pack_h2((a[0] * cs0 - a[1] * sn0) * scale, (a[1] * cs0 + a[0] * sn0) * scale);
                *(uint32_t*)(Cc + (size_t)(row + 8) * ldc + col) =
                    pack_h2((a[2] * cs1 - a[3] * sn1) * scale, (a[3] * cs1 + a[2] * sn1) * scale);
            } else {
                *(uint32_t*)(Cc + (size_t)row * ldc + col)       = pack_h2(a[0], a[1]);
                *(uint32_t*)(Cc + (size_t)(row + 8) * ldc + col) = pack_h2(a[2], a[3]);
            }
        });
}

// ======================= tensor-core attention (head-paired, R15) ================
#define A2_QA 0
#define A2_QB 32768
#define A2_KH 65536
#define A2_VH 98304
#define A2_PA 131072
#define A2_PB 139264
#define A2_DA 147456
#define A2_DB 147712
#define A2_SMEM 147968

__global__ __launch_bounds__(256, 1)
void attn_tc(const __half* __restrict__ qh, const __half* __restrict__ kkh,
             const __half* __restrict__ vvh, __half* __restrict__ avh)
{
    extern __shared__ char sm[];
    const uint32_t sb = smem_u32(sm);
    const int qt = blockIdx.x, khd = blockIdx.y, b = blockIdx.z;
    const int n0h = khd * 2;
    const int t0  = qt * 64;
    const int tid = threadIdx.x, wid = tid >> 5, lane = tid & 31;
    const int lrow = lane & 15, lk = lane >> 4;
    const int wm = wid & 1, wn = wid >> 1;
    const int wq = wid & 1, wh = wid >> 1;
    float* denA = (float*)(sm + A2_DA);
    float* denB = (float*)(sm + A2_DB);

    auto load_one = [&](uint32_t dh, const __half* gh, size_t base, int stride) {
        #pragma unroll
        for (int i = 0; i < 8; ++i) {
            int u = tid + i * 256;
            int row = u >> 5, unit = u & 31;
            int su = (unit & 24) | ((unit ^ row) & 7);
            cp16(dh + (row << 9) + (su << 4), gh + base + (size_t)row * stride + unit * 8);
        }
    };

    int jt0 = qt - 16; if (jt0 < 0) jt0 = 0;
    const size_t qbase0 = ((size_t)(b * Ss + t0) * NQh + n0h) * Hh;
    const size_t kv0    = ((size_t)(b * Ss + jt0 * 64) * NKVh + khd) * Hh;
    load_one(sb + A2_QA, qh, qbase0, NQh * Hh);
    load_one(sb + A2_QB, qh, qbase0 + Hh, NQh * Hh);
    load_one(sb + A2_KH, kkh, kv0, NKVh * Hh);
    cp_commit();
    load_one(sb + A2_VH, vvh, kv0, NKVh * Hh);
    cp_commit();

    if (tid < 64) { denA[tid] = 0.f; denB[tid] = 0.f; }

    float o[2][2][8][4];
    #pragma unroll
    for (int hd = 0; hd < 2; ++hd)
        #pragma unroll
        for (int pi = 0; pi < 2; ++pi)
            #pragma unroll
            for (int i = 0; i < 8; ++i)
                #pragma unroll
                for (int e = 0; e < 4; ++e) o[hd][pi][i][e] = 0.f;
    float dreg[2][2][2] = {};

    for (int jt = jt0; jt <= qt; ++jt) {
        const int kb = jt * 64;
        const bool lastt = (jt == qt);
        const bool farTile = (qt >= 16) && (jt == qt - 16);
        cp_wait1();
        __syncthreads();

        float sacc[2][2][2][4] = {};
        const bool skipS = (farTile && (16 * wn + 15 <= 32 * wm)) ||
                           (lastt   && (16 * wn > 32 * wm + 31));
        if (!skipS) {
            #pragma unroll
            for (int ks = 0; ks < 16; ++ks) {
                uint32_t aqA[2][4], aqB[2][4], bk[4];
                const int u = ks * 2 + lk;
                {
                    int r = wn * 16 + lrow;
                    int su = (u & 24) | ((u ^ r) & 7);
                    ldsm_x4(bk, sb + A2_KH + (r << 9) + (su << 4));
                }
                #pragma unroll
                for (int mi = 0; mi < 2; ++mi) {
                    int r = wm * 32 + mi * 16 + lrow;
                    int su = (u & 24) | ((u ^ r) & 7);
                    ldsm_x4(aqA[mi], sb + A2_QA + (r << 9) + (su << 4));
                    ldsm_x4(aqB[mi], sb + A2_QB + (r << 9) + (su << 4));
                }
                #pragma unroll
                for (int mi = 0; mi < 2; ++mi)
                    #pragma unroll
                    for (int ni = 0; ni < 2; ++ni) {
                        mma_f16(sacc[0][mi][ni], aqA[mi], bk[ni], bk[ni + 2]);
                        mma_f16(sacc[1][mi][ni], aqB[mi], bk[ni], bk[ni + 2]);
                    }
            }
        }

        #pragma unroll
        for (int hd = 0; hd < 2; ++hd) {
            char* Pbase = sm + (hd ? A2_PB : A2_PA);
            #pragma unroll
            for (int mi = 0; mi < 2; ++mi)
                #pragma unroll
                for (int eo = 0; eo < 2; ++eo) {
                    const int row = wm * 32 + mi * 16 + (lane >> 2) + eo * 8;
                    const int tg  = t0 + row;
                    #pragma unroll
                    for (int ni = 0; ni < 2; ++ni) {
                        const int c0 = wn * 16 + ni * 8 + (lane & 3) * 2;
                        const int k0g = kb + c0;
                        float p0 = softcap_exp(sacc[hd][mi][ni][eo * 2 + 0], k0g     <= tg && k0g     > tg - WIN);
                        float p1 = softcap_exp(sacc[hd][mi][ni][eo * 2 + 1], k0g + 1 <= tg && k0g + 1 > tg - WIN);
                        dreg[hd][mi][eo] += p0 + p1;
                        const int su = (wn * 2 + ni) ^ (row & 7);
                        uint32_t pa = (uint32_t)(row << 7) + (su << 4) + (lane & 3) * 4;
                        *(uint32_t*)(Pbase + pa) = pack_h2(p0, p1);
                    }
                }
        }
        __syncthreads();
        if (!lastt) {
            load_one(sb + A2_KH, kkh,
                     ((size_t)(b * Ss + kb + 64) * NKVh + khd) * Hh, NKVh * Hh);
            cp_commit();
        }
        if (!lastt) cp_wait1(); else cp_wait0();
        __syncthreads();

        #pragma unroll
        for (int ks = 0; ks < 4; ++ks) {
            const bool skipP = (farTile && (16 * ks + 15 <= 32 * wq)) ||
                               (lastt   && (16 * ks > 32 * wq + 31));
            if (skipP) continue;
            uint32_t phA[2][4], phB[2][4];
            #pragma unroll
            for (int pi = 0; pi < 2; ++pi) {
                const int r = wq * 32 + pi * 16 + lrow;
                const int u = ks * 2 + lk;
                const int su = (u ^ r) & 7;
                ldsm_x4(phA[pi], sb + A2_PA + (r << 7) + (su << 4));
                ldsm_x4(phB[pi], sb + A2_PB + (r << 7) + (su << 4));
            }
            const int slot = lane >> 3;
            const int key  = ks * 16 + (slot & 1) * 8 + (lane & 7);
            #pragma unroll
            for (int hb = 0; hb < 4; ++hb) {
                uint32_t v4h[4];
                const int hu = wh * 8 + hb * 2 + (slot >> 1);
                const int su = (hu & 24) | ((hu ^ key) & 7);
                ldsm_x4_t(v4h, sb + A2_VH + (key << 9) + (su << 4));
                #pragma unroll
                for (int pi = 0; pi < 2; ++pi)
                    #pragma unroll
                    for (int no = 0; no < 2; ++no) {
                        mma_f16(o[0][pi][hb * 2 + no], phA[pi], v4h[no * 2], v4h[no * 2 + 1]);
                        mma_f16(o[1][pi][hb * 2 + no], phB[pi], v4h[no * 2], v4h[no * 2 + 1]);
                    }
            }
        }
        __syncthreads();
        if (!lastt) {
            load_one(sb + A2_VH, vvh,
                     ((size_t)(b * Ss + kb + 64) * NKVh + khd) * Hh, NKVh * Hh);
            cp_commit();
        }
    }

    #pragma unroll
    for (int hd = 0; hd < 2; ++hd) {
        float* den = hd ? denB : denA;
        #pragma unroll
        for (int mi = 0; mi < 2; ++mi)
            #pragma unroll
            for (int eo = 0; eo < 2; ++eo) {
                float d = dreg[hd][mi][eo];
                d += __shfl_xor_sync(0xffffffff, d, 1);
                d += __shfl_xor_sync(0xffffffff, d, 2);
                if ((lane & 3) == 0)
                    atomicAdd(&den[wm * 32 + mi * 16 + (lane >> 2) + eo * 8], d);
            }
    }
    __syncthreads();

    #pragma unroll
    for (int hd = 0; hd < 2; ++hd) {
        float* den = hd ? denB : denA;
        #pragma unroll
        for (int pi = 0; pi < 2; ++pi) {
            const int r0 = wq * 32 + pi * 16 + (lane >> 2);
            const float inv0 = 1.f / den[r0];
            const float inv1 = 1.f / den[r0 + 8];
            const size_t gr0 = ((size_t)(b * Ss + t0 + r0) * NQh + n0h + hd) * Hh;
            const size_t gr1 = ((size_t)(b * Ss + t0 + r0 + 8) * NQh + n0h + hd) * Hh;
            #pragma unroll
            for (int hb = 0; hb < 4; ++hb)
                #pragma unroll
                for (int no = 0; no < 2; ++no) {
                    const int col = wh * 64 + hb * 16 + no * 8 + (lane & 3) * 2;
                    const float* a = o[hd][pi][hb * 2 + no];
                    *(uint32_t*)(avh + gr0 + col) = pack_h2(a[0] * inv0, a[1] * inv0);
                    *(uint32_t*)(avh + gr1 + col) = pack_h2(a[2] * inv1, a[3] * inv1);
                }
        }
    }
}

// ======================= launch ==================================================
extern "C" void kernel_launch(void* const* d_in, const int* in_sizes, int n_in,
                              void* d_out, int out_size)
{
    (void)in_sizes; (void)n_in; (void)out_size;
    const float* x  = (const float*)d_in[0];
    const float* Wq = (const float*)d_in[1];
    const float* Wk = (const float*)d_in[2];
    const float* Wv = (const float*)d_in[3];
    const float* Wo = (const float*)d_in[4];
    float* out = (float*)d_out;

    __half *xh, *wqh, *wkh, *wvh, *woh, *qh, *kh, *vh, *avh;
    cudaGetSymbolAddress((void**)&xh,  g_xh);
    cudaGetSymbolAddress((void**)&wqh, g_wqh);
    cudaGetSymbolAddress((void**)&wkh, g_wkh);
    cudaGetSymbolAddress((void**)&wvh, g_wvh);
    cudaGetSymbolAddress((void**)&woh, g_woh);
    cudaGetSymbolAddress((void**)&qh,  g_qh);
    cudaGetSymbolAddress((void**)&kh,  g_kh);
    cudaGetSymbolAddress((void**)&vh,  g_vh);
    cudaGetSymbolAddress((void**)&avh, g_avh);

    cudaFuncSetAttribute(gemm_tc,  cudaFuncAttributeMaxDynamicSharedMemorySize, GT_SMEM);
    cudaFuncSetAttribute(gemm_qkv, cudaFuncAttributeMaxDynamicSharedMemorySize, GT_SMEM);
    cudaFuncSetAttribute(attn_tc,  cudaFuncAttributeMaxDynamicSharedMemorySize, A2_SMEM);

    // single unified conversion launch (x + 4 weights + rope table)
    conv_all_kernel<<<33792, 256>>>((const float4*)x, Wq, Wk, Wv, Wo,
                                    xh, wqh, wkh, wvh, woh);

    // merged QKV projection (fused rope epilogues)
    gemm_qkv<<<dim3(32, 64), 256, GT_SMEM>>>(xh, wqh, wkh, wvh, qh, kh, vh);

    // tensor-core attention (head-paired, wide warp tiles, boundary skips)
    attn_tc<<<dim3(Ss / 64, NKVh, Bb), 256, A2_SMEM>>>(qh, kh, vh, avh);

    // output projection
    gemm_tc<<<dim3(32, 16), 256, GT_SMEM>>>(avh, woh, out, 4096, 2048);
}